// round 4
// baseline (speedup 1.0000x reference)
#include <cuda_runtime.h>
#include <cstdint>

#define NCTA     125
#define NTHREADS 256         // 8 warps: pair (w, w+4) owns rows 4w..4w+3
#define RDIM     2000
#define CEXT     2048        // 2000 h + 28 x + 20 zero pad
#define XDIM     28
#define TSTEPS   28
#define BATCH    512
#define NSTEP    (BATCH*TSTEPS)
#define ODIM     10

// Static device scratch (no allocation anywhere)
__device__ float    g_h[2][CEXT];          // double-buffered [h | x_t | 0pad]
__device__ float    g_hlast[BATCH*RDIM];   // h at t = T-1 per batch element
__device__ unsigned g_ctr;                 // single grid counter (R1-proven)

// ---- packed f32x2 helpers ----
__device__ __forceinline__ unsigned long long fma2(unsigned long long a,
                                                   unsigned long long b,
                                                   unsigned long long c) {
    unsigned long long d;
    asm("fma.rn.f32x2 %0, %1, %2, %3;" : "=l"(d) : "l"(a), "l"(b), "l"(c));
    return d;
}
__device__ __forceinline__ unsigned long long pk2(float lo, float hi) {
    unsigned long long u;
    asm("mov.b64 %0, {%1, %2};" : "=l"(u)
        : "r"(__float_as_uint(lo)), "r"(__float_as_uint(hi)));
    return u;
}
__device__ __forceinline__ float lo32(unsigned long long v) { return __uint_as_float((unsigned)v); }
__device__ __forceinline__ float hi32(unsigned long long v) { return __uint_as_float((unsigned)(v >> 32)); }

// W_ext element: [W_res | W_in | 0-pad], row r, extended column c
__device__ __forceinline__ float wext(const float* __restrict__ Wres,
                                      const float* __restrict__ Win,
                                      int r, int c) {
    if (c < RDIM)        return Wres[r * RDIM + c];
    if (c < RDIM + XDIM) return Win[r * XDIM + (c - RDIM)];
    return 0.0f;
}

__global__ void reset_kernel(const float* __restrict__ x) {
    const int t = blockIdx.x * blockDim.x + threadIdx.x;
    if (t == 0)    g_ctr = 0u;
    if (t < RDIM)  g_h[1][t] = 0.0f;                           // h0 = 0
    if (t >= RDIM && t < RDIM + XDIM) g_h[1][t] = x[t - RDIM]; // x_0
    if (t >= RDIM + XDIM && t < CEXT) { g_h[1][t] = 0.0f; g_h[0][t] = 0.0f; }
}

__global__ void __launch_bounds__(NTHREADS, 1)
rnn_kernel(const float* __restrict__ x,
           const float* __restrict__ W_in,
           const float* __restrict__ W_res) {
    __shared__ __align__(16) float sh[CEXT];
    __shared__ __align__(16) float spart[4][4];   // per-pair partial row sums

    const int tid  = threadIdx.x;
    const int w    = tid >> 5;
    const int l    = tid & 31;
    const int p    = w & 3;          // pair id 0..3
    const int half = w >> 2;         // 0: cols 0-1023, 1: cols 1024-2047
    const int r0   = blockIdx.x * 16 + 4 * p;     // pair's 4 rows
    const int cb   = half * 1024 + 4 * l;         // lane column base
    const bool xduty = (blockIdx.x == 0 && w == 7 && l == 0); // never on publish path

    // ---- W_ext slice in registers: 4 rows x 32 cols per lane = 64 u64 ----
    unsigned long long W2[4][8][2];
#pragma unroll
    for (int i = 0; i < 4; ++i)
#pragma unroll
        for (int k = 0; k < 8; ++k)
#pragma unroll
            for (int j = 0; j < 2; ++j) {
                const int c = cb + 128 * k + 2 * j;
                W2[i][k][j] = pk2(wext(W_res, W_in, r0 + i, c),
                                  wext(W_res, W_in, r0 + i, c + 1));
            }

    const unsigned long long z2 = pk2(0.f, 0.f);

    for (int s = 0; s < NSTEP; ++s) {
        // ---- prefetch x_{s+1} (CTA0 warp7 lane0; off the publish path) ----
        float4 xr[7];
        if (xduty && s + 1 < NSTEP) {
            const float4* xp = (const float4*)(x + (size_t)(s + 1) * XDIM);
#pragma unroll
            for (int j = 0; j < 7; ++j) xr[j] = __ldg(xp + j);
        }

        // ---- wait: tid0 polls the single counter (R1-proven topology) ----
        if (tid == 0) {
            const unsigned target = (unsigned)s * NCTA;
            unsigned v;
            do {
                asm volatile("ld.acquire.gpu.u32 %0, [%1];"
                             : "=r"(v) : "l"(&g_ctr) : "memory");
            } while (v < target);
        }
        __syncthreads();   // A

        // ---- stage h_ext (2048 floats) into SMEM, fully coalesced ----
        const float4* src = (const float4*)g_h[(s + 1) & 1];
        float4 v0 = __ldcg(src + tid);
        float4 v1 = __ldcg(src + tid + 256);
        ((float4*)sh)[tid]       = v0;
        ((float4*)sh)[tid + 256] = v1;
        __syncthreads();   // B

        // ---- matvec: 4 rows x 32 cols per lane over this warp's half ----
        unsigned long long acc[4][2];
#pragma unroll
        for (int i = 0; i < 4; ++i) { acc[i][0] = z2; acc[i][1] = z2; }
#pragma unroll
        for (int k = 0; k < 8; ++k) {
            const ulonglong2 h2 = *(const ulonglong2*)(sh + cb + 128 * k);
#pragma unroll
            for (int i = 0; i < 4; ++i) {
                acc[i][0] = fma2(W2[i][k][0], h2.x, acc[i][0]);
                acc[i][1] = fma2(W2[i][k][1], h2.y, acc[i][1]);
            }
        }
        float rs[4];
#pragma unroll
        for (int i = 0; i < 4; ++i)
            rs[i] = (lo32(acc[i][0]) + hi32(acc[i][0]))
                  + (lo32(acc[i][1]) + hi32(acc[i][1]));

        // ---- butterfly: 4 independent chains, 5 stages ----
#pragma unroll
        for (int m = 16; m >= 1; m >>= 1) {
#pragma unroll
            for (int i = 0; i < 4; ++i)
                rs[i] += __shfl_xor_sync(0xffffffffu, rs[i], m);
        }

        // ---- upper-half warps publish partials to SMEM ----
        if (half == 1 && l == 0)
            *(float4*)spart[p] = make_float4(rs[0], rs[1], rs[2], rs[3]);

        // ---- x_{s+1} into next buffer (race-free; off publish path) ----
        if (xduty && s + 1 < NSTEP) {
            float4* xd = (float4*)&g_h[s & 1][RDIM];
#pragma unroll
            for (int j = 0; j < 7; ++j) __stcg(xd + j, xr[j]);
        }
        __syncthreads();   // C

        // ---- lower-half warps combine + tanh + publish (float4/pair) ----
        if (half == 0 && l == 0) {
            const float4 q = *(const float4*)spart[p];
            float4 hv;
            hv.x = tanhf(rs[0] + q.x);
            hv.y = tanhf(rs[1] + q.y);
            hv.z = tanhf(rs[2] + q.z);
            hv.w = tanhf(rs[3] + q.w);
            __stcg((float4*)&g_h[s & 1][r0], hv);
            if ((s % TSTEPS) == TSTEPS - 1)
                *(float4*)&g_hlast[(s / TSTEPS) * RDIM + r0] = hv;
        }
        __syncthreads();   // D: all stores done before arrive
        if (tid == 0)
            asm volatile("red.release.gpu.global.add.u32 [%0], %1;"
                         :: "l"(&g_ctr), "r"(1u) : "memory");
    }
}

__global__ void out_kernel(const float* __restrict__ W_out,
                           float* __restrict__ out) {
    const int b   = blockIdx.x;
    const int tid = threadIdx.x;
    const float* __restrict__ h = g_hlast + b * RDIM;

    float acc[ODIM];
#pragma unroll
    for (int o = 0; o < ODIM; ++o) acc[o] = 0.f;

    for (int k = tid; k < RDIM; k += 256) {
        const float hv = h[k];
#pragma unroll
        for (int o = 0; o < ODIM; ++o)
            acc[o] = fmaf(W_out[o * RDIM + k], hv, acc[o]);
    }
#pragma unroll
    for (int o = 0; o < ODIM; ++o) {
#pragma unroll
        for (int m = 16; m >= 1; m >>= 1)
            acc[o] += __shfl_xor_sync(0xffffffffu, acc[o], m);
    }
    __shared__ float sp[8][ODIM];
    if ((tid & 31) == 0) {
#pragma unroll
        for (int o = 0; o < ODIM; ++o) sp[tid >> 5][o] = acc[o];
    }
    __syncthreads();
    if (tid < ODIM) {
        float s2 = 0.f;
#pragma unroll
        for (int ww = 0; ww < 8; ++ww) s2 += sp[ww][tid];
        out[b * ODIM + tid] = s2;
    }
}

extern "C" void kernel_launch(void* const* d_in, const int* in_sizes, int n_in,
                              void* d_out, int out_size) {
    (void)in_sizes; (void)n_in; (void)out_size;
    const float* x     = (const float*)d_in[0];
    const float* W_in  = (const float*)d_in[1];
    const float* W_res = (const float*)d_in[2];
    const float* W_out = (const float*)d_in[3];
    float* out = (float*)d_out;

    reset_kernel<<<16, 256>>>(x);                    // counter + h0 + x_0 + pads
    rnn_kernel<<<NCTA, NTHREADS>>>(x, W_in, W_res);  // 125 CTAs, 1/SM
    out_kernel<<<BATCH, 256>>>(W_out, out);
}

// round 5
// speedup vs baseline: 1.3257x; 1.3257x over previous
#include <cuda_runtime.h>
#include <cstdint>

#define NCTA     125
#define ROWS     16          // rows per CTA
#define NTHREADS 256         // 8 warps; warp w reads h cols [256w, 256w+256)
#define RDIM     2000
#define XDIM     28
#define TSTEPS   28
#define BATCH    512
#define NSTEP    (BATCH*TSTEPS)
#define ODIM     10
#define NGRP     8           // 8 column groups of 256 = 16 producer CTAs each

// Static device scratch (no allocation anywhere)
__device__ __align__(16) float g_h[2][2048];   // double-buffered hidden state
__device__ float    g_hlast[BATCH*RDIM];       // h at t = T-1 per batch element
__device__ unsigned g_ctr[NGRP * 32];          // per-group counters, 128B apart

// ---- packed f32x2 helpers ----
__device__ __forceinline__ unsigned long long fma2(unsigned long long a,
                                                   unsigned long long b,
                                                   unsigned long long c) {
    unsigned long long d;
    asm("fma.rn.f32x2 %0, %1, %2, %3;" : "=l"(d) : "l"(a), "l"(b), "l"(c));
    return d;
}
__device__ __forceinline__ unsigned long long mul2(unsigned long long a,
                                                   unsigned long long b) {
    unsigned long long d;
    asm("mul.rn.f32x2 %0, %1, %2;" : "=l"(d) : "l"(a), "l"(b));
    return d;
}
__device__ __forceinline__ unsigned long long pk2(float lo, float hi) {
    unsigned long long u;
    asm("mov.b64 %0, {%1, %2};" : "=l"(u)
        : "r"(__float_as_uint(lo)), "r"(__float_as_uint(hi)));
    return u;
}
__device__ __forceinline__ float lo32(unsigned long long v) { return __uint_as_float((unsigned)v); }
__device__ __forceinline__ float hi32(unsigned long long v) { return __uint_as_float((unsigned)(v >> 32)); }

// W_ext element: [W_res | W_in | 0-pad], row r, extended column c
__device__ __forceinline__ float wext(const float* __restrict__ Wres,
                                      const float* __restrict__ Win,
                                      int r, int c) {
    if (c < RDIM)        return Wres[r * RDIM + c];
    if (c < RDIM + XDIM) return Win[r * XDIM + (c - RDIM)];
    return 0.0f;
}

// R1-validated register reduce-scatter stage
template <int M, int HALF>
__device__ __forceinline__ void rs_stage(float* a, int l) {
    const bool up = (l & M) != 0;
#pragma unroll
    for (int i = 0; i < HALF; ++i) {
        float send = up ? a[i] : a[i + HALF];
        float recv = __shfl_xor_sync(0xffffffffu, send, M);
        a[i] = (up ? a[i + HALF] : a[i]) + recv;
    }
}

__global__ void reset_kernel() {
    const int t = blockIdx.x * blockDim.x + threadIdx.x;
    if (t < NGRP * 32) g_ctr[t] = 0u;
    if (t < RDIM)      g_h[1][t] = 0.0f;   // h0 = 0 (buffer read by step 0)
}

__global__ void __launch_bounds__(NTHREADS, 1)
rnn_kernel(const float* __restrict__ x,
           const float* __restrict__ W_in,
           const float* __restrict__ W_res) {
    __shared__ float spart[8][ROWS];   // per-warp partial row sums (512 B)

    const int tid   = threadIdx.x;
    const int w     = tid >> 5;
    const int l     = tid & 31;
    const int rbase = blockIdx.x * ROWS;
    const int c0    = w * 256 + l * 4;          // lane's column base (R1 layout)
    const unsigned ng = (w < 7) ? 16u : 13u;    // producers in this warp's group
    unsigned tgt = 0u;                           // poll target = s * ng

    // x-duty lanes: warp 7, cols chunk B = [1920,2048); lanes 20..26 carry x
    const bool xlane = (w == 7) && (l >= 20) && (l < 27);
    const bool zlane = (w == 7) && (l >= 27);

    // ---- W_ext slice in registers (R1 gather, 128 regs) ----
    unsigned long long W2[ROWS][4];
#pragma unroll
    for (int r = 0; r < ROWS; ++r) {
        const int gr = rbase + r;
#pragma unroll
        for (int q = 0; q < 4; ++q) {
            const int c = c0 + (q >> 1) * 128 + (q & 1) * 2;
            W2[r][q] = pk2(wext(W_res, W_in, gr, c),
                           wext(W_res, W_in, gr, c + 1));
        }
    }

    const unsigned* __restrict__ cp = &g_ctr[w * 32];
    unsigned* __restrict__ ap = &g_ctr[(blockIdx.x >> 4) * 32];

    for (int s = 0; s < NSTEP; ++s) {
        // ---- per-warp gate: wait for this warp's 256-col producer group ----
        unsigned v;
        do {
            asm volatile("ld.acquire.gpu.u32 %0, [%1];"
                         : "=r"(v) : "l"(cp) : "memory");
        } while (v < tgt);
        tgt += ng;

        // ---- load this lane's 8 h-columns straight into registers ----
        const float* __restrict__ buf = g_h[(s + 1) & 1];
        ulonglong2 ha = __ldcg((const ulonglong2*)(buf + c0));
        ulonglong2 hb;
        if (xlane) {            // cols 2000..2027 come from x_s (read-only input)
            const float4 xv = __ldg((const float4*)(x + (size_t)s * XDIM) + (l - 20));
            hb.x = pk2(xv.x, xv.y);
            hb.y = pk2(xv.z, xv.w);
        } else if (zlane) {     // cols 2028..2047: zero pad
            hb.x = pk2(0.f, 0.f);
            hb.y = pk2(0.f, 0.f);
        } else {
            hb = __ldcg((const ulonglong2*)(buf + c0 + 128));
        }

        // ---- matvec: 16 rows x 8 cols per lane, packed f32x2 (R1 order) ----
        unsigned long long acc[ROWS];
#pragma unroll
        for (int r = 0; r < ROWS; ++r) acc[r] = mul2(W2[r][0], ha.x);
#pragma unroll
        for (int r = 0; r < ROWS; ++r) acc[r] = fma2(W2[r][1], ha.y, acc[r]);
#pragma unroll
        for (int r = 0; r < ROWS; ++r) acc[r] = fma2(W2[r][2], hb.x, acc[r]);
#pragma unroll
        for (int r = 0; r < ROWS; ++r) acc[r] = fma2(W2[r][3], hb.y, acc[r]);

        float a[ROWS];
#pragma unroll
        for (int r = 0; r < ROWS; ++r) a[r] = lo32(acc[r]) + hi32(acc[r]);

        // ---- R1-validated warp reduce-scatter (16 rows over 32 lanes) ----
        rs_stage<16, 8>(a, l);
        rs_stage<8, 4>(a, l);
        rs_stage<4, 2>(a, l);
        rs_stage<2, 1>(a, l);
        float pv = a[0] + __shfl_xor_sync(0xffffffffu, a[0], 1);

        __syncthreads();   // bar1: warp 0 finished reading previous spart
        if ((l & 1) == 0) spart[w][l >> 1] = pv;
        __syncthreads();   // bar2: spart ready

        // ---- warp 0: combine + tanh + publish + release-arrive ----
        if (w == 0) {
            if (l < ROWS) {
                float sum = spart[0][l];
#pragma unroll
                for (int ww = 1; ww < 8; ++ww) sum += spart[ww][l];
                const float hv = tanhf(sum);
                __stcg(&g_h[s & 1][rbase + l], hv);
                if ((s % TSTEPS) == TSTEPS - 1)
                    g_hlast[(s / TSTEPS) * RDIM + rbase + l] = hv;
            }
            __syncwarp();
            if (l == 0)
                asm volatile("red.release.gpu.global.add.u32 [%0], %1;"
                             :: "l"(ap), "r"(1u) : "memory");
        }
        // other warps proceed straight to their next-step poll
    }
}

__global__ void out_kernel(const float* __restrict__ W_out,
                           float* __restrict__ out) {
    const int b   = blockIdx.x;
    const int tid = threadIdx.x;
    const float* __restrict__ h = g_hlast + b * RDIM;

    float acc[ODIM];
#pragma unroll
    for (int o = 0; o < ODIM; ++o) acc[o] = 0.f;

    for (int k = tid; k < RDIM; k += 256) {
        const float hv = h[k];
#pragma unroll
        for (int o = 0; o < ODIM; ++o)
            acc[o] = fmaf(W_out[o * RDIM + k], hv, acc[o]);
    }
#pragma unroll
    for (int o = 0; o < ODIM; ++o) {
#pragma unroll
        for (int m = 16; m >= 1; m >>= 1)
            acc[o] += __shfl_xor_sync(0xffffffffu, acc[o], m);
    }
    __shared__ float sp[8][ODIM];
    if ((tid & 31) == 0) {
#pragma unroll
        for (int o = 0; o < ODIM; ++o) sp[tid >> 5][o] = acc[o];
    }
    __syncthreads();
    if (tid < ODIM) {
        float s2 = 0.f;
#pragma unroll
        for (int ww = 0; ww < 8; ++ww) s2 += sp[ww][tid];
        out[b * ODIM + tid] = s2;
    }
}

extern "C" void kernel_launch(void* const* d_in, const int* in_sizes, int n_in,
                              void* d_out, int out_size) {
    (void)in_sizes; (void)n_in; (void)out_size;
    const float* x     = (const float*)d_in[0];
    const float* W_in  = (const float*)d_in[1];
    const float* W_res = (const float*)d_in[2];
    const float* W_out = (const float*)d_in[3];
    float* out = (float*)d_out;

    reset_kernel<<<8, 256>>>();                      // counters + h0 each replay
    rnn_kernel<<<NCTA, NTHREADS>>>(x, W_in, W_res);  // 125 CTAs, 1/SM
    out_kernel<<<BATCH, 256>>>(W_out, out);
}